// round 1
// baseline (speedup 1.0000x reference)
#include <cuda_runtime.h>
#include <math.h>

#define NPTS 16384
#define FD   512
#define MD   128
#define BM   64
#define BN   64
#define NKV  (NPTS / BN)
#define QS_STRIDE 132
#define KS_STRIDE 132
#define SS_STRIDE 65

// Scratch (device globals: allocation-free rule)
__device__ float g_Q[NPTS * MD];     // 8 MB
__device__ float g_K[NPTS * MD];     // 8 MB
__device__ float g_V[NPTS * FD];     // 32 MB
__device__ float g_att[NPTS * FD];   // 32 MB

// ---------------------------------------------------------------------------
// Tiled SGEMM with bias: C[rowBase:+128, colBase:+128] = A @ B + bias
// A: [Nrows, Kd] row-major, B: [Kd, Nc] row-major. All dims multiples of tile.
// ---------------------------------------------------------------------------
__global__ __launch_bounds__(256) void sgemm_bias_kernel(
    const float* __restrict__ A, const float* __restrict__ B,
    const float* __restrict__ bias, float* __restrict__ C,
    int Kd, int Nc)
{
    __shared__ float As[16][132];   // transposed: As[k][m], padded
    __shared__ float Bs[16][128];   // Bs[k][n]

    const int tid = threadIdx.x;
    const int ty  = tid >> 4;       // 0..15
    const int tx  = tid & 15;       // 0..15
    const int rowBase = blockIdx.y * 128;
    const int colBase = blockIdx.x * 128;

    const int arow = tid >> 2;          // 0..63
    const int acol = (tid & 3) * 4;     // 0,4,8,12
    const int brow = tid >> 5;          // 0..7
    const int bcol = (tid & 31) * 4;    // 0..124

    float acc[8][8];
#pragma unroll
    for (int i = 0; i < 8; i++)
#pragma unroll
        for (int j = 0; j < 8; j++) acc[i][j] = 0.f;

    for (int k0 = 0; k0 < Kd; k0 += 16) {
        float4 a0 = *(const float4*)(A + (size_t)(rowBase + arow)      * Kd + k0 + acol);
        float4 a1 = *(const float4*)(A + (size_t)(rowBase + arow + 64) * Kd + k0 + acol);
        float4 b0 = *(const float4*)(B + (size_t)(k0 + brow)     * Nc + colBase + bcol);
        float4 b1 = *(const float4*)(B + (size_t)(k0 + brow + 8) * Nc + colBase + bcol);

        __syncthreads();   // previous-iteration fragment reads done
        As[acol + 0][arow]      = a0.x;
        As[acol + 1][arow]      = a0.y;
        As[acol + 2][arow]      = a0.z;
        As[acol + 3][arow]      = a0.w;
        As[acol + 0][arow + 64] = a1.x;
        As[acol + 1][arow + 64] = a1.y;
        As[acol + 2][arow + 64] = a1.z;
        As[acol + 3][arow + 64] = a1.w;
        *(float4*)&Bs[brow][bcol]     = b0;
        *(float4*)&Bs[brow + 8][bcol] = b1;
        __syncthreads();

#pragma unroll
        for (int k = 0; k < 16; k++) {
            float4 av0 = *(const float4*)&As[k][ty * 8];
            float4 av1 = *(const float4*)&As[k][ty * 8 + 4];
            float4 bv0 = *(const float4*)&Bs[k][tx * 8];
            float4 bv1 = *(const float4*)&Bs[k][tx * 8 + 4];
            float ar[8] = {av0.x, av0.y, av0.z, av0.w, av1.x, av1.y, av1.z, av1.w};
            float br[8] = {bv0.x, bv0.y, bv0.z, bv0.w, bv1.x, bv1.y, bv1.z, bv1.w};
#pragma unroll
            for (int i = 0; i < 8; i++)
#pragma unroll
                for (int j = 0; j < 8; j++)
                    acc[i][j] = fmaf(ar[i], br[j], acc[i][j]);
        }
    }

    float4 bia0 = *(const float4*)(bias + colBase + tx * 8);
    float4 bia1 = *(const float4*)(bias + colBase + tx * 8 + 4);
#pragma unroll
    for (int i = 0; i < 8; i++) {
        float* cp = C + (size_t)(rowBase + ty * 8 + i) * Nc + colBase + tx * 8;
        float4 o0 = make_float4(acc[i][0] + bia0.x, acc[i][1] + bia0.y,
                                acc[i][2] + bia0.z, acc[i][3] + bia0.w);
        float4 o1 = make_float4(acc[i][4] + bia1.x, acc[i][5] + bia1.y,
                                acc[i][6] + bia1.z, acc[i][7] + bia1.w);
        *(float4*)cp       = o0;
        *(float4*)(cp + 4) = o1;
    }
}

// ---------------------------------------------------------------------------
// Flash attention (fp32, online softmax). One CTA = 64 query rows x full dv=512.
// 256 threads: tr = tid>>5 (8 row-groups), tc = tid&31 (32 col-groups).
// Thread owns rows tr*8+i (i<8), output cols tc*4 + 128u + e (u<4, e<4).
// ---------------------------------------------------------------------------
__global__ __launch_bounds__(256, 1) void flash_kernel(
    const float* __restrict__ Q, const float* __restrict__ K,
    const float* __restrict__ V, float* __restrict__ O)
{
    extern __shared__ float sm[];
    float* Qs   = sm;                          // 64*132
    float* Ks   = Qs + BM * QS_STRIDE;         // 64*132
    float* Vs   = Ks + BN * KS_STRIDE;         // 64*512
    float* Ss   = Vs + BN * FD;                // 64*65
    float* mrow = Ss + BM * SS_STRIDE;         // 64
    float* lrow = mrow + BM;                   // 64
    float* crow = lrow + BM;                   // 64

    const int tid = threadIdx.x;
    const int tr  = tid >> 5;     // 0..7
    const int tc  = tid & 31;     // 0..31
    const int qb  = blockIdx.x;

    // Load Q block [64 x 128] (row = tid>>2, quarter = tid&3 covers 32 cols)
    {
        const int row = tid >> 2;
        const int q4  = (tid & 3) * 32;
        const float* gq = Q + (size_t)(qb * BM + row) * MD + q4;
        float* sq = Qs + row * QS_STRIDE + q4;
#pragma unroll
        for (int e = 0; e < 8; e++)
            *(float4*)(sq + 4 * e) = *(const float4*)(gq + 4 * e);
    }
    if (tid < BM) { mrow[tid] = -1e30f; lrow[tid] = 0.f; }

    float acc[8][16];
#pragma unroll
    for (int i = 0; i < 8; i++)
#pragma unroll
        for (int u = 0; u < 16; u++) acc[i][u] = 0.f;

    const float scale = 0.08838834764831845f;   // 1/sqrt(128)

    for (int kb = 0; kb < NKV; kb++) {
        __syncthreads();   // previous iteration's Ks/Vs reads done; Qs visible

        // Load K block [64 x 128]
        {
            const int row = tid >> 2;
            const int q4  = (tid & 3) * 32;
            const float* gk = K + (size_t)(kb * BN + row) * MD + q4;
            float* sk = Ks + row * KS_STRIDE + q4;
#pragma unroll
            for (int e = 0; e < 8; e++)
                *(float4*)(sk + 4 * e) = *(const float4*)(gk + 4 * e);
        }
        // Load V block [64 x 512] linearly (8192 float4s / 256 threads)
        {
            const float4* gv = (const float4*)(V + (size_t)kb * BN * FD);
            float4* sv = (float4*)Vs;
#pragma unroll
            for (int e = 0; e < 32; e++)
                sv[tid + 256 * e] = gv[tid + 256 * e];
        }
        __syncthreads();

        // S = Qblk @ Kblk^T  (each thread: 8 rows x cols {tc, tc+32})
        float s0[8], s1[8];
#pragma unroll
        for (int i = 0; i < 8; i++) { s0[i] = 0.f; s1[i] = 0.f; }
#pragma unroll 8
        for (int k = 0; k < MD; k += 4) {
            float4 kv0 = *(const float4*)(Ks + tc * KS_STRIDE + k);
            float4 kv1 = *(const float4*)(Ks + (tc + 32) * KS_STRIDE + k);
#pragma unroll
            for (int i = 0; i < 8; i++) {
                float4 qv = *(const float4*)(Qs + (tr * 8 + i) * QS_STRIDE + k);
                s0[i] = fmaf(qv.x, kv0.x, s0[i]);
                s0[i] = fmaf(qv.y, kv0.y, s0[i]);
                s0[i] = fmaf(qv.z, kv0.z, s0[i]);
                s0[i] = fmaf(qv.w, kv0.w, s0[i]);
                s1[i] = fmaf(qv.x, kv1.x, s1[i]);
                s1[i] = fmaf(qv.y, kv1.y, s1[i]);
                s1[i] = fmaf(qv.z, kv1.z, s1[i]);
                s1[i] = fmaf(qv.w, kv1.w, s1[i]);
            }
        }
#pragma unroll
        for (int i = 0; i < 8; i++) {
            Ss[(tr * 8 + i) * SS_STRIDE + tc]      = s0[i] * scale;
            Ss[(tr * 8 + i) * SS_STRIDE + tc + 32] = s1[i] * scale;
        }
        __syncthreads();

        // Online softmax: 4 threads per row (srow = tid>>2, sq = tid&3 -> 16 cols)
        {
            const int srow = tid >> 2;
            const int sq   = tid & 3;
            float* rowp = Ss + srow * SS_STRIDE + sq * 16;
            float m_old = mrow[srow];
            float mx = m_old;
#pragma unroll
            for (int j = 0; j < 16; j++) mx = fmaxf(mx, rowp[j]);
            mx = fmaxf(mx, __shfl_xor_sync(0xffffffffu, mx, 1));
            mx = fmaxf(mx, __shfl_xor_sync(0xffffffffu, mx, 2));
            float sum = 0.f;
#pragma unroll
            for (int j = 0; j < 16; j++) {
                float p = __expf(rowp[j] - mx);
                rowp[j] = p;
                sum += p;
            }
            sum += __shfl_xor_sync(0xffffffffu, sum, 1);
            sum += __shfl_xor_sync(0xffffffffu, sum, 2);
            if (sq == 0) {
                float corr = __expf(m_old - mx);
                crow[srow] = corr;
                lrow[srow] = lrow[srow] * corr + sum;
                mrow[srow] = mx;
            }
        }
        __syncthreads();

        // Rescale accumulators by correction factor
#pragma unroll
        for (int i = 0; i < 8; i++) {
            float c = crow[tr * 8 + i];
#pragma unroll
            for (int u = 0; u < 16; u++) acc[i][u] *= c;
        }

        // acc += P @ Vblk   (thread cols: tc*4 + 128u + e)
#pragma unroll 4
        for (int j = 0; j < BN; j++) {
            const float* vb = Vs + j * FD + tc * 4;
            float4 v0 = *(const float4*)(vb);
            float4 v1 = *(const float4*)(vb + 128);
            float4 v2 = *(const float4*)(vb + 256);
            float4 v3 = *(const float4*)(vb + 384);
#pragma unroll
            for (int i = 0; i < 8; i++) {
                float p = Ss[(tr * 8 + i) * SS_STRIDE + j];
                acc[i][0]  = fmaf(p, v0.x, acc[i][0]);
                acc[i][1]  = fmaf(p, v0.y, acc[i][1]);
                acc[i][2]  = fmaf(p, v0.z, acc[i][2]);
                acc[i][3]  = fmaf(p, v0.w, acc[i][3]);
                acc[i][4]  = fmaf(p, v1.x, acc[i][4]);
                acc[i][5]  = fmaf(p, v1.y, acc[i][5]);
                acc[i][6]  = fmaf(p, v1.z, acc[i][6]);
                acc[i][7]  = fmaf(p, v1.w, acc[i][7]);
                acc[i][8]  = fmaf(p, v2.x, acc[i][8]);
                acc[i][9]  = fmaf(p, v2.y, acc[i][9]);
                acc[i][10] = fmaf(p, v2.z, acc[i][10]);
                acc[i][11] = fmaf(p, v2.w, acc[i][11]);
                acc[i][12] = fmaf(p, v3.x, acc[i][12]);
                acc[i][13] = fmaf(p, v3.y, acc[i][13]);
                acc[i][14] = fmaf(p, v3.z, acc[i][14]);
                acc[i][15] = fmaf(p, v3.w, acc[i][15]);
            }
        }
    }

    // Epilogue: divide by softmax denominator, write out
#pragma unroll
    for (int i = 0; i < 8; i++) {
        float inv = 1.f / lrow[tr * 8 + i];
        float* op = O + (size_t)(qb * BM + tr * 8 + i) * FD + tc * 4;
        float4 o0 = make_float4(acc[i][0] * inv,  acc[i][1] * inv,
                                acc[i][2] * inv,  acc[i][3] * inv);
        float4 o1 = make_float4(acc[i][4] * inv,  acc[i][5] * inv,
                                acc[i][6] * inv,  acc[i][7] * inv);
        float4 o2 = make_float4(acc[i][8] * inv,  acc[i][9] * inv,
                                acc[i][10] * inv, acc[i][11] * inv);
        float4 o3 = make_float4(acc[i][12] * inv, acc[i][13] * inv,
                                acc[i][14] * inv, acc[i][15] * inv);
        *(float4*)(op)       = o0;
        *(float4*)(op + 128) = o1;
        *(float4*)(op + 256) = o2;
        *(float4*)(op + 384) = o3;
    }
}

// ---------------------------------------------------------------------------
// kernel_launch
// ---------------------------------------------------------------------------
extern "C" void kernel_launch(void* const* d_in, const int* in_sizes, int n_in,
                              void* d_out, int out_size)
{
    const float* x  = (const float*)d_in[0];
    const float* Wq = (const float*)d_in[1];
    const float* bq = (const float*)d_in[2];
    const float* Wk = (const float*)d_in[3];
    const float* bk = (const float*)d_in[4];
    const float* Wv = (const float*)d_in[5];
    const float* bv = (const float*)d_in[6];
    const float* Wo = (const float*)d_in[7];
    const float* bo = (const float*)d_in[8];
    float* out = (float*)d_out;

    float *pQ, *pK, *pV, *pA;
    cudaGetSymbolAddress((void**)&pQ, g_Q);
    cudaGetSymbolAddress((void**)&pK, g_K);
    cudaGetSymbolAddress((void**)&pV, g_V);
    cudaGetSymbolAddress((void**)&pA, g_att);

    const size_t FLASH_SMEM =
        (size_t)(BM * QS_STRIDE + BN * KS_STRIDE + BN * FD + BM * SS_STRIDE + 3 * BM)
        * sizeof(float);
    cudaFuncSetAttribute(flash_kernel,
                         cudaFuncAttributeMaxDynamicSharedMemorySize,
                         (int)FLASH_SMEM);

    dim3 blk(256);
    // Q = x @ Wq + bq  [16384, 128]
    sgemm_bias_kernel<<<dim3(1, 128), blk>>>(x, Wq, bq, pQ, FD, MD);
    // K = x @ Wk + bk  [16384, 128]
    sgemm_bias_kernel<<<dim3(1, 128), blk>>>(x, Wk, bk, pK, FD, MD);
    // V = x @ Wv + bv  [16384, 512]
    sgemm_bias_kernel<<<dim3(4, 128), blk>>>(x, Wv, bv, pV, FD, FD);
    // atten = softmax(Q K^T / sqrt(M)) V   [16384, 512]
    flash_kernel<<<NPTS / BM, 256, FLASH_SMEM>>>(pQ, pK, pV, pA);
    // out = atten @ Wo + bo  [16384, 512]
    sgemm_bias_kernel<<<dim3(4, 128), blk>>>(pA, Wo, bo, out, FD, FD);
}

// round 4
// speedup vs baseline: 2.5439x; 2.5439x over previous
#include <cuda_runtime.h>

#define NPTS 16384
#define FD   512
#define MD   128
#define BM   64
#define BN   64
#define NKV  (NPTS / BN)

// Shared-memory strides chosen for conflict-free fragment access:
//  A-frag pattern (g*S + t): S=132 -> 4g+t bijective; S=36 -> 4g+t; S=72 -> 8g+t
//  B-frag pattern (t*S + g): S=520 -> 8t+g; S=136 -> 8t+g
#define QS_STRIDE 132
#define KS_STRIDE 132
#define SS_STRIDE 72
#define VS_STRIDE 520

// Scratch (device globals: allocation-free rule)
__device__ float g_Q[NPTS * MD];
__device__ float g_K[NPTS * MD];
__device__ float g_V[NPTS * FD];
__device__ float g_att[NPTS * FD];

// ---------------------------------------------------------------------------
// helpers
// ---------------------------------------------------------------------------
__device__ __forceinline__ float cvt_tf32(float x) {
    unsigned u;
    asm("cvt.rna.tf32.f32 %0, %1;" : "=r"(u) : "f"(x));
    return __uint_as_float(u);
}
__device__ __forceinline__ unsigned fu(float x) { return __float_as_uint(x); }

// D += A(16x8) * B(8x8), tf32 inputs (bit patterns in unsigned), fp32 accum
__device__ __forceinline__ void mma8(float* d, const unsigned* a, const unsigned* b) {
    asm volatile(
        "mma.sync.aligned.m16n8k8.row.col.f32.tf32.tf32.f32 "
        "{%0,%1,%2,%3}, {%4,%5,%6,%7}, {%8,%9}, {%0,%1,%2,%3};"
        : "+f"(d[0]), "+f"(d[1]), "+f"(d[2]), "+f"(d[3])
        : "r"(a[0]), "r"(a[1]), "r"(a[2]), "r"(a[3]), "r"(b[0]), "r"(b[1]));
}

// ---------------------------------------------------------------------------
// TF32 tensor-core GEMM: C[128 x 128 tile] = A @ B + bias
// A: [Nrows, Kd] row-major, B: [Kd, Nc] row-major. 256 threads, 8 warps (4m x 2n).
// ---------------------------------------------------------------------------
#define AS_STRIDE 36
#define BS_STRIDE 136
__global__ __launch_bounds__(256) void gemm_tf32_kernel(
    const float* __restrict__ A, const float* __restrict__ B,
    const float* __restrict__ bias, float* __restrict__ C,
    int Kd, int Nc)
{
    __shared__ float As[128 * AS_STRIDE];   // A[m][k], k-chunk = 32
    __shared__ float Bs[32 * BS_STRIDE];    // B[k][n], n = 128

    const int tid  = threadIdx.x;
    const int w    = tid >> 5;
    const int lane = tid & 31;
    const int g    = lane >> 2;
    const int t    = lane & 3;
    const int wm   = w & 3;                 // 4 m-groups of 32 rows
    const int wn   = w >> 2;                // 2 n-groups of 64 cols
    const int rowBase = blockIdx.y * 128;
    const int colBase = blockIdx.x * 128;

    float acc[2][8][4];
#pragma unroll
    for (int mt = 0; mt < 2; mt++)
#pragma unroll
        for (int nt = 0; nt < 8; nt++)
#pragma unroll
            for (int e = 0; e < 4; e++) acc[mt][nt][e] = 0.f;

    for (int k0 = 0; k0 < Kd; k0 += 32) {
        // stage gmem
        float4 areg[4], breg[4];
#pragma unroll
        for (int e = 0; e < 4; e++) {
            int f4 = tid + 256 * e;           // 1024 float4s: 128 rows x 8
            int ar = f4 >> 3, ac4 = f4 & 7;
            areg[e] = *(const float4*)(A + (size_t)(rowBase + ar) * Kd + k0 + ac4 * 4);
            int br = f4 >> 5, bc4 = f4 & 31;  // 32 rows x 32
            breg[e] = *(const float4*)(B + (size_t)(k0 + br) * Nc + colBase + bc4 * 4);
        }
        __syncthreads();
#pragma unroll
        for (int e = 0; e < 4; e++) {
            int f4 = tid + 256 * e;
            int ar = f4 >> 3, ac4 = f4 & 7;
            float4 v = areg[e];
            v.x = cvt_tf32(v.x); v.y = cvt_tf32(v.y);
            v.z = cvt_tf32(v.z); v.w = cvt_tf32(v.w);
            *(float4*)(As + ar * AS_STRIDE + ac4 * 4) = v;
            int br = f4 >> 5, bc4 = f4 & 31;
            float4 u = breg[e];
            u.x = cvt_tf32(u.x); u.y = cvt_tf32(u.y);
            u.z = cvt_tf32(u.z); u.w = cvt_tf32(u.w);
            *(float4*)(Bs + br * BS_STRIDE + bc4 * 4) = u;
        }
        __syncthreads();

#pragma unroll
        for (int kt = 0; kt < 4; kt++) {
            unsigned afr[2][4];
#pragma unroll
            for (int mt = 0; mt < 2; mt++) {
                const float* ap = As + (wm * 32 + mt * 16) * AS_STRIDE + kt * 8;
                afr[mt][0] = fu(ap[g * AS_STRIDE + t]);
                afr[mt][1] = fu(ap[(g + 8) * AS_STRIDE + t]);
                afr[mt][2] = fu(ap[g * AS_STRIDE + t + 4]);
                afr[mt][3] = fu(ap[(g + 8) * AS_STRIDE + t + 4]);
            }
#pragma unroll
            for (int nt = 0; nt < 8; nt++) {
                const float* bp = Bs + wn * 64 + nt * 8;
                unsigned bfr[2];
                bfr[0] = fu(bp[(kt * 8 + t) * BS_STRIDE + g]);
                bfr[1] = fu(bp[(kt * 8 + t + 4) * BS_STRIDE + g]);
#pragma unroll
                for (int mt = 0; mt < 2; mt++) mma8(acc[mt][nt], afr[mt], bfr);
            }
        }
    }

    // epilogue
#pragma unroll
    for (int mt = 0; mt < 2; mt++) {
        int r0 = rowBase + wm * 32 + mt * 16;
#pragma unroll
        for (int nt = 0; nt < 8; nt++) {
            int col = colBase + wn * 64 + nt * 8 + 2 * t;
            float b0 = bias[col], b1 = bias[col + 1];
            float2 lo = make_float2(acc[mt][nt][0] + b0, acc[mt][nt][1] + b1);
            float2 hi = make_float2(acc[mt][nt][2] + b0, acc[mt][nt][3] + b1);
            *(float2*)(C + (size_t)(r0 + g)     * Nc + col) = lo;
            *(float2*)(C + (size_t)(r0 + g + 8) * Nc + col) = hi;
        }
    }
}

// ---------------------------------------------------------------------------
// Flash attention, TF32 tensor cores. CTA = 64 q-rows, iterate 64 keys.
// 256 threads / 8 warps: wm = w&1 (32 rows), wn = w>>1 (S: 16 cols, PV: 128 cols)
// ---------------------------------------------------------------------------
__global__ __launch_bounds__(256, 1) void flash_kernel(
    const float* __restrict__ Q, const float* __restrict__ K,
    const float* __restrict__ V, float* __restrict__ O)
{
    extern __shared__ float sm[];
    float* Qs   = sm;                           // 64*132
    float* Ks   = Qs + BM * QS_STRIDE;          // 64*132
    float* Vs   = Ks + BN * KS_STRIDE;          // 64*520
    float* Ss   = Vs + BN * VS_STRIDE;          // 64*72
    float* mrow = Ss + BM * SS_STRIDE;
    float* lrow = mrow + BM;
    float* crow = lrow + BM;

    const int tid  = threadIdx.x;
    const int w    = tid >> 5;
    const int lane = tid & 31;
    const int g    = lane >> 2;
    const int t    = lane & 3;
    const int wm   = w & 1;
    const int wn   = w >> 1;
    const int qb   = blockIdx.x;

    // Load Q block [64 x 128], convert to tf32
    {
        const int row = tid >> 2;
        const int q4  = (tid & 3) * 32;
        const float* gq = Q + (size_t)(qb * BM + row) * MD + q4;
        float* sq = Qs + row * QS_STRIDE + q4;
#pragma unroll
        for (int e = 0; e < 8; e++) {
            float4 v = *(const float4*)(gq + 4 * e);
            v.x = cvt_tf32(v.x); v.y = cvt_tf32(v.y);
            v.z = cvt_tf32(v.z); v.w = cvt_tf32(v.w);
            *(float4*)(sq + 4 * e) = v;
        }
    }
    if (tid < BM) { mrow[tid] = -1e30f; lrow[tid] = 0.f; }

    float oacc[2][16][4];
#pragma unroll
    for (int mt = 0; mt < 2; mt++)
#pragma unroll
        for (int nt = 0; nt < 16; nt++)
#pragma unroll
            for (int e = 0; e < 4; e++) oacc[mt][nt][e] = 0.f;

    const float scale = 0.08838834764831845f;   // 1/sqrt(128)

    for (int kb = 0; kb < NKV; kb++) {
        __syncthreads();   // guard Ks/Vs reuse

        // Load K block [64 x 128] -> tf32
        {
            const int row = tid >> 2;
            const int q4  = (tid & 3) * 32;
            const float* gk = K + (size_t)(kb * BN + row) * MD + q4;
            float* sk = Ks + row * KS_STRIDE + q4;
#pragma unroll
            for (int e = 0; e < 8; e++) {
                float4 v = *(const float4*)(gk + 4 * e);
                v.x = cvt_tf32(v.x); v.y = cvt_tf32(v.y);
                v.z = cvt_tf32(v.z); v.w = cvt_tf32(v.w);
                *(float4*)(sk + 4 * e) = v;
            }
        }
        // Load V block [64 x 512] -> tf32
        {
            const float4* gv = (const float4*)(V + (size_t)kb * BN * FD);
#pragma unroll
            for (int e = 0; e < 32; e++) {
                int f4  = tid + 256 * e;
                int row = f4 >> 7, c4 = f4 & 127;
                float4 v = gv[f4];
                v.x = cvt_tf32(v.x); v.y = cvt_tf32(v.y);
                v.z = cvt_tf32(v.z); v.w = cvt_tf32(v.w);
                *(float4*)(Vs + row * VS_STRIDE + c4 * 4) = v;
            }
        }
        __syncthreads();

        // S = Q @ K^T : warp covers rows wm*32 (2 tiles), cols wn*16 (2 tiles)
        float sacc[2][2][4];
#pragma unroll
        for (int mt = 0; mt < 2; mt++)
#pragma unroll
            for (int nt = 0; nt < 2; nt++)
#pragma unroll
                for (int e = 0; e < 4; e++) sacc[mt][nt][e] = 0.f;

#pragma unroll
        for (int kt = 0; kt < 16; kt++) {
            unsigned afr[2][4];
#pragma unroll
            for (int mt = 0; mt < 2; mt++) {
                const float* qp = Qs + (wm * 32 + mt * 16) * QS_STRIDE + kt * 8;
                afr[mt][0] = fu(qp[g * QS_STRIDE + t]);
                afr[mt][1] = fu(qp[(g + 8) * QS_STRIDE + t]);
                afr[mt][2] = fu(qp[g * QS_STRIDE + t + 4]);
                afr[mt][3] = fu(qp[(g + 8) * QS_STRIDE + t + 4]);
            }
#pragma unroll
            for (int nt = 0; nt < 2; nt++) {
                const float* kp = Ks + (wn * 16 + nt * 8) * KS_STRIDE + kt * 8;
                unsigned bfr[2];
                bfr[0] = fu(kp[g * KS_STRIDE + t]);
                bfr[1] = fu(kp[g * KS_STRIDE + t + 4]);
#pragma unroll
                for (int mt = 0; mt < 2; mt++) mma8(sacc[mt][nt], afr[mt], bfr);
            }
        }
        // store scaled scores to Ss
#pragma unroll
        for (int mt = 0; mt < 2; mt++) {
            int r0 = wm * 32 + mt * 16;
#pragma unroll
            for (int nt = 0; nt < 2; nt++) {
                int c0 = wn * 16 + nt * 8 + 2 * t;
                *(float2*)(Ss + (r0 + g) * SS_STRIDE + c0) =
                    make_float2(sacc[mt][nt][0] * scale, sacc[mt][nt][1] * scale);
                *(float2*)(Ss + (r0 + g + 8) * SS_STRIDE + c0) =
                    make_float2(sacc[mt][nt][2] * scale, sacc[mt][nt][3] * scale);
            }
        }
        __syncthreads();

        // Online softmax: 4 threads per row, 16 cols each; P written as tf32
        {
            const int srow = tid >> 2;
            const int sq   = tid & 3;
            float* rowp = Ss + srow * SS_STRIDE + sq * 16;
            float m_old = mrow[srow];
            float mx = m_old;
#pragma unroll
            for (int j = 0; j < 16; j++) mx = fmaxf(mx, rowp[j]);
            mx = fmaxf(mx, __shfl_xor_sync(0xffffffffu, mx, 1));
            mx = fmaxf(mx, __shfl_xor_sync(0xffffffffu, mx, 2));
            float sum = 0.f;
#pragma unroll
            for (int j = 0; j < 16; j++) {
                float p = __expf(rowp[j] - mx);
                sum += p;
                rowp[j] = cvt_tf32(p);
            }
            sum += __shfl_xor_sync(0xffffffffu, sum, 1);
            sum += __shfl_xor_sync(0xffffffffu, sum, 2);
            if (sq == 0) {
                float corr = __expf(m_old - mx);
                crow[srow] = corr;
                lrow[srow] = lrow[srow] * corr + sum;
                mrow[srow] = mx;
            }
        }
        __syncthreads();

        // Rescale accumulators
#pragma unroll
        for (int mt = 0; mt < 2; mt++) {
            int r0 = wm * 32 + mt * 16;
            float c_lo = crow[r0 + g];
            float c_hi = crow[r0 + g + 8];
#pragma unroll
            for (int nt = 0; nt < 16; nt++) {
                oacc[mt][nt][0] *= c_lo; oacc[mt][nt][1] *= c_lo;
                oacc[mt][nt][2] *= c_hi; oacc[mt][nt][3] *= c_hi;
            }
        }

        // O += P @ V : warp covers rows wm*32 (2 tiles), V-cols wn*128 (16 tiles)
#pragma unroll
        for (int kt = 0; kt < 8; kt++) {
            unsigned afr[2][4];
#pragma unroll
            for (int mt = 0; mt < 2; mt++) {
                const float* pp = Ss + (wm * 32 + mt * 16) * SS_STRIDE + kt * 8;
                afr[mt][0] = fu(pp[g * SS_STRIDE + t]);
                afr[mt][1] = fu(pp[(g + 8) * SS_STRIDE + t]);
                afr[mt][2] = fu(pp[g * SS_STRIDE + t + 4]);
                afr[mt][3] = fu(pp[(g + 8) * SS_STRIDE + t + 4]);
            }
#pragma unroll
            for (int nt = 0; nt < 16; nt++) {
                const float* vp = Vs + kt * 8 * VS_STRIDE + wn * 128 + nt * 8;
                unsigned bfr[2];
                bfr[0] = fu(vp[t * VS_STRIDE + g]);
                bfr[1] = fu(vp[(t + 4) * VS_STRIDE + g]);
#pragma unroll
                for (int mt = 0; mt < 2; mt++) mma8(oacc[mt][nt], afr[mt], bfr);
            }
        }
    }

    // Epilogue
#pragma unroll
    for (int mt = 0; mt < 2; mt++) {
        int r0 = wm * 32 + mt * 16;
        float inv_lo = 1.f / lrow[r0 + g];
        float inv_hi = 1.f / lrow[r0 + g + 8];
#pragma unroll
        for (int nt = 0; nt < 16; nt++) {
            int col = wn * 128 + nt * 8 + 2 * t;
            *(float2*)(O + (size_t)(qb * BM + r0 + g) * FD + col) =
                make_float2(oacc[mt][nt][0] * inv_lo, oacc[mt][nt][1] * inv_lo);
            *(float2*)(O + (size_t)(qb * BM + r0 + g + 8) * FD + col) =
                make_float2(oacc[mt][nt][2] * inv_hi, oacc[mt][nt][3] * inv_hi);
        }
    }
}

// ---------------------------------------------------------------------------
// kernel_launch
// ---------------------------------------------------------------------------
extern "C" void kernel_launch(void* const* d_in, const int* in_sizes, int n_in,
                              void* d_out, int out_size)
{
    const float* x  = (const float*)d_in[0];
    const float* Wq = (const float*)d_in[1];
    const float* bq = (const float*)d_in[2];
    const float* Wk = (const float*)d_in[3];
    const float* bk = (const float*)d_in[4];
    const float* Wv = (const float*)d_in[5];
    const float* bv = (const float*)d_in[6];
    const float* Wo = (const float*)d_in[7];
    const float* bo = (const float*)d_in[8];
    float* out = (float*)d_out;

    float *pQ, *pK, *pV, *pA;
    cudaGetSymbolAddress((void**)&pQ, g_Q);
    cudaGetSymbolAddress((void**)&pK, g_K);
    cudaGetSymbolAddress((void**)&pV, g_V);
    cudaGetSymbolAddress((void**)&pA, g_att);

    const size_t FLASH_SMEM =
        (size_t)(BM * QS_STRIDE + BN * KS_STRIDE + BN * VS_STRIDE + BM * SS_STRIDE + 3 * BM)
        * sizeof(float);
    cudaFuncSetAttribute(flash_kernel,
                         cudaFuncAttributeMaxDynamicSharedMemorySize,
                         (int)FLASH_SMEM);

    dim3 blk(256);
    gemm_tf32_kernel<<<dim3(1, 128), blk>>>(x, Wq, bq, pQ, FD, MD);
    gemm_tf32_kernel<<<dim3(1, 128), blk>>>(x, Wk, bk, pK, FD, MD);
    gemm_tf32_kernel<<<dim3(4, 128), blk>>>(x, Wv, bv, pV, FD, FD);
    flash_kernel<<<NPTS / BM, 256, FLASH_SMEM>>>(pQ, pK, pV, pA);
    gemm_tf32_kernel<<<dim3(4, 128), blk>>>(pA, Wo, bo, out, FD, FD);
}

// round 5
// speedup vs baseline: 2.7386x; 1.0766x over previous
#include <cuda_runtime.h>
#include <cstdint>

#define NPTS 16384
#define FD   512
#define MD   128
#define BM   64
#define BN   64
#define NKV  (NPTS / BN)

#define QS 132   // chunk stride 33 === 1 mod 8 -> ldsm conflict-free
#define KS 132
#define SS 68    // chunk stride 17 === 1 mod 8 -> ldsm conflict-free

// Scratch (device globals: allocation-free rule)
__device__ float g_Q[NPTS * MD];
__device__ float g_K[NPTS * MD];
__device__ float g_V[NPTS * FD];
__device__ float g_att[NPTS * FD];

// ---------------------------------------------------------------------------
// helpers
// ---------------------------------------------------------------------------
__device__ __forceinline__ float cvt_tf32(float x) {
    unsigned u;
    asm("cvt.rna.tf32.f32 %0, %1;" : "=r"(u) : "f"(x));
    return __uint_as_float(u);
}
__device__ __forceinline__ unsigned fu(float x) { return __float_as_uint(x); }

__device__ __forceinline__ uint32_t sptr(const void* p) {
    return (uint32_t)__cvta_generic_to_shared(p);
}

// ldmatrix x4: full tf32 m16k8 A-fragment in one instruction.
__device__ __forceinline__ void ldsm_x4(unsigned* r, uint32_t a) {
    asm volatile("ldmatrix.sync.aligned.m8n8.x4.shared.b16 {%0,%1,%2,%3}, [%4];"
                 : "=r"(r[0]), "=r"(r[1]), "=r"(r[2]), "=r"(r[3]) : "r"(a));
}
// ldmatrix x2: tf32 n8k8 B-fragment in one instruction.
__device__ __forceinline__ void ldsm_x2(unsigned* r, uint32_t a) {
    asm volatile("ldmatrix.sync.aligned.m8n8.x2.shared.b16 {%0,%1}, [%2];"
                 : "=r"(r[0]), "=r"(r[1]) : "r"(a));
}

// D += A(16x8) * B(8x8), tf32 inputs, fp32 accum
__device__ __forceinline__ void mma8(float* d, const unsigned* a, const unsigned* b) {
    asm volatile(
        "mma.sync.aligned.m16n8k8.row.col.f32.tf32.tf32.f32 "
        "{%0,%1,%2,%3}, {%4,%5,%6,%7}, {%8,%9}, {%0,%1,%2,%3};"
        : "+f"(d[0]), "+f"(d[1]), "+f"(d[2]), "+f"(d[3])
        : "r"(a[0]), "r"(a[1]), "r"(a[2]), "r"(a[3]), "r"(b[0]), "r"(b[1]));
}

// ---------------------------------------------------------------------------
// TF32 tensor-core GEMM (unchanged from R4): C[128x128 tile] = A @ B + bias
// ---------------------------------------------------------------------------
#define AS_STRIDE 36
#define BS_STRIDE 136
__global__ __launch_bounds__(256) void gemm_tf32_kernel(
    const float* __restrict__ A, const float* __restrict__ B,
    const float* __restrict__ bias, float* __restrict__ C,
    int Kd, int Nc)
{
    __shared__ float As[128 * AS_STRIDE];
    __shared__ float Bs[32 * BS_STRIDE];

    const int tid  = threadIdx.x;
    const int w    = tid >> 5;
    const int lane = tid & 31;
    const int g    = lane >> 2;
    const int t    = lane & 3;
    const int wm   = w & 3;
    const int wn   = w >> 2;
    const int rowBase = blockIdx.y * 128;
    const int colBase = blockIdx.x * 128;

    float acc[2][8][4];
#pragma unroll
    for (int mt = 0; mt < 2; mt++)
#pragma unroll
        for (int nt = 0; nt < 8; nt++)
#pragma unroll
            for (int e = 0; e < 4; e++) acc[mt][nt][e] = 0.f;

    for (int k0 = 0; k0 < Kd; k0 += 32) {
        float4 areg[4], breg[4];
#pragma unroll
        for (int e = 0; e < 4; e++) {
            int f4 = tid + 256 * e;
            int ar = f4 >> 3, ac4 = f4 & 7;
            areg[e] = *(const float4*)(A + (size_t)(rowBase + ar) * Kd + k0 + ac4 * 4);
            int br = f4 >> 5, bc4 = f4 & 31;
            breg[e] = *(const float4*)(B + (size_t)(k0 + br) * Nc + colBase + bc4 * 4);
        }
        __syncthreads();
#pragma unroll
        for (int e = 0; e < 4; e++) {
            int f4 = tid + 256 * e;
            int ar = f4 >> 3, ac4 = f4 & 7;
            float4 v = areg[e];
            v.x = cvt_tf32(v.x); v.y = cvt_tf32(v.y);
            v.z = cvt_tf32(v.z); v.w = cvt_tf32(v.w);
            *(float4*)(As + ar * AS_STRIDE + ac4 * 4) = v;
            int br = f4 >> 5, bc4 = f4 & 31;
            float4 u = breg[e];
            u.x = cvt_tf32(u.x); u.y = cvt_tf32(u.y);
            u.z = cvt_tf32(u.z); u.w = cvt_tf32(u.w);
            *(float4*)(Bs + br * BS_STRIDE + bc4 * 4) = u;
        }
        __syncthreads();

#pragma unroll
        for (int kt = 0; kt < 4; kt++) {
            unsigned afr[2][4];
#pragma unroll
            for (int mt = 0; mt < 2; mt++) {
                const float* ap = As + (wm * 32 + mt * 16) * AS_STRIDE + kt * 8;
                afr[mt][0] = fu(ap[g * AS_STRIDE + t]);
                afr[mt][1] = fu(ap[(g + 8) * AS_STRIDE + t]);
                afr[mt][2] = fu(ap[g * AS_STRIDE + t + 4]);
                afr[mt][3] = fu(ap[(g + 8) * AS_STRIDE + t + 4]);
            }
#pragma unroll
            for (int nt = 0; nt < 8; nt++) {
                const float* bp = Bs + wn * 64 + nt * 8;
                unsigned bfr[2];
                bfr[0] = fu(bp[(kt * 8 + t) * BS_STRIDE + g]);
                bfr[1] = fu(bp[(kt * 8 + t + 4) * BS_STRIDE + g]);
#pragma unroll
                for (int mt = 0; mt < 2; mt++) mma8(acc[mt][nt], afr[mt], bfr);
            }
        }
    }

#pragma unroll
    for (int mt = 0; mt < 2; mt++) {
        int r0 = rowBase + wm * 32 + mt * 16;
#pragma unroll
        for (int nt = 0; nt < 8; nt++) {
            int col = colBase + wn * 64 + nt * 8 + 2 * t;
            float b0 = bias[col], b1 = bias[col + 1];
            float2 lo = make_float2(acc[mt][nt][0] + b0, acc[mt][nt][1] + b1);
            float2 hi = make_float2(acc[mt][nt][2] + b0, acc[mt][nt][3] + b1);
            *(float2*)(C + (size_t)(r0 + g)     * Nc + col) = lo;
            *(float2*)(C + (size_t)(r0 + g + 8) * Nc + col) = hi;
        }
    }
}

// ---------------------------------------------------------------------------
// Flash attention v2: ldmatrix fragments, V direct from L2 (no smem staging).
// 8 warps. S-phase: wm=w&1 (32 rows), wn=w>>1 (16 cols).
// PV-phase: each warp: all 64 rows (mt 0..3) x 64 V-cols (w*64..w*64+63).
// ---------------------------------------------------------------------------
__global__ __launch_bounds__(256, 1) void flash_kernel(
    const float* __restrict__ Q, const float* __restrict__ K,
    const float* __restrict__ V, float* __restrict__ O)
{
    extern __shared__ float sm[];
    float* Qs   = sm;                 // 64*132
    float* Ks   = Qs + BM * QS;       // 64*132
    float* Ss   = Ks + BN * KS;       // 64*68
    float* mrow = Ss + BM * SS;
    float* lrow = mrow + BM;
    float* crow = lrow + BM;

    const int tid  = threadIdx.x;
    const int w    = tid >> 5;
    const int lane = tid & 31;
    const int g    = lane >> 2;
    const int t    = lane & 3;
    const int wm   = w & 1;
    const int wn   = w >> 1;
    const int qb   = blockIdx.x;

    // ldmatrix per-lane geometry:
    // x4 (A 16x8): lanes 0-7 rows 0-7 col 0 | 8-15 rows 8-15 col 0 |
    //              16-23 rows 0-7 col 4 | 24-31 rows 8-15 col 4
    const int a_r = (lane & 7) | (lane & 8);        // 0..15
    const int a_c = (lane >> 4) * 4;                // 0 or 4
    // x2 (B 8x8): lanes 0-7 rows col 0 | 8-15 rows col 4 (16-31 replicate)
    const int b_r = lane & 7;
    const int b_c = ((lane >> 3) & 1) * 4;

    const uint32_t qs_b = sptr(Qs), ks_b = sptr(Ks), ss_b = sptr(Ss);

    // Load Q block [64 x 128] -> tf32
    {
        const int row = tid >> 2;
        const int q4  = (tid & 3) * 32;
        const float* gq = Q + (size_t)(qb * BM + row) * MD + q4;
        float* sq = Qs + row * QS + q4;
#pragma unroll
        for (int e = 0; e < 8; e++) {
            float4 v = *(const float4*)(gq + 4 * e);
            v.x = cvt_tf32(v.x); v.y = cvt_tf32(v.y);
            v.z = cvt_tf32(v.z); v.w = cvt_tf32(v.w);
            *(float4*)(sq + 4 * e) = v;
        }
    }
    if (tid < BM) { mrow[tid] = -1e30f; lrow[tid] = 0.f; }

    float oacc[4][8][4];
#pragma unroll
    for (int mt = 0; mt < 4; mt++)
#pragma unroll
        for (int nt = 0; nt < 8; nt++)
#pragma unroll
            for (int e = 0; e < 4; e++) oacc[mt][nt][e] = 0.f;

    const float scale = 0.08838834764831845f;   // 1/sqrt(128)

    for (int kb = 0; kb < NKV; kb++) {
        // Stage K block [64 x 128] -> tf32 (Ss/Ks reads of prev iter done:
        // all warps passed the post-softmax sync before reaching PV/here)
        {
            const int row = tid >> 2;
            const int q4  = (tid & 3) * 32;
            const float* gk = K + (size_t)(kb * BN + row) * MD + q4;
            float* sk = Ks + row * KS + q4;
#pragma unroll
            for (int e = 0; e < 8; e++) {
                float4 v = *(const float4*)(gk + 4 * e);
                v.x = cvt_tf32(v.x); v.y = cvt_tf32(v.y);
                v.z = cvt_tf32(v.z); v.w = cvt_tf32(v.w);
                *(float4*)(sk + 4 * e) = v;
            }
        }
        __syncthreads();   // K staged; prev-iter PV Ss reads complete

        // ---- S = Q @ K^T ----
        float sacc[2][2][4];
#pragma unroll
        for (int mt = 0; mt < 2; mt++)
#pragma unroll
            for (int nt = 0; nt < 2; nt++)
#pragma unroll
                for (int e = 0; e < 4; e++) sacc[mt][nt][e] = 0.f;

#pragma unroll
        for (int kt = 0; kt < 16; kt++) {
            unsigned afr[2][4];
#pragma unroll
            for (int mt = 0; mt < 2; mt++)
                ldsm_x4(afr[mt],
                        qs_b + 4u * ((wm * 32 + mt * 16 + a_r) * QS + kt * 8 + a_c));
#pragma unroll
            for (int nt = 0; nt < 2; nt++) {
                unsigned bfr[2];
                ldsm_x2(bfr,
                        ks_b + 4u * ((wn * 16 + nt * 8 + b_r) * KS + kt * 8 + b_c));
                mma8(sacc[0][nt], afr[0], bfr);
                mma8(sacc[1][nt], afr[1], bfr);
            }
        }
#pragma unroll
        for (int mt = 0; mt < 2; mt++) {
            int r0 = wm * 32 + mt * 16;
#pragma unroll
            for (int nt = 0; nt < 2; nt++) {
                int c0 = wn * 16 + nt * 8 + 2 * t;
                *(float2*)(Ss + (r0 + g) * SS + c0) =
                    make_float2(sacc[mt][nt][0] * scale, sacc[mt][nt][1] * scale);
                *(float2*)(Ss + (r0 + g + 8) * SS + c0) =
                    make_float2(sacc[mt][nt][2] * scale, sacc[mt][nt][3] * scale);
            }
        }
        __syncthreads();

        // ---- Online softmax (conflict-free col map: col = sq + 4j) ----
        {
            const int srow = tid >> 2;
            const int sq   = tid & 3;
            float* rowp = Ss + srow * SS;
            float m_old = mrow[srow];
            float mx = m_old;
#pragma unroll
            for (int j = 0; j < 16; j++) mx = fmaxf(mx, rowp[sq + 4 * j]);
            mx = fmaxf(mx, __shfl_xor_sync(0xffffffffu, mx, 1));
            mx = fmaxf(mx, __shfl_xor_sync(0xffffffffu, mx, 2));
            float sum = 0.f;
#pragma unroll
            for (int j = 0; j < 16; j++) {
                float p = __expf(rowp[sq + 4 * j] - mx);
                sum += p;
                rowp[sq + 4 * j] = cvt_tf32(p);
            }
            sum += __shfl_xor_sync(0xffffffffu, sum, 1);
            sum += __shfl_xor_sync(0xffffffffu, sum, 2);
            if (sq == 0) {
                float corr = __expf(m_old - mx);
                crow[srow] = corr;
                lrow[srow] = lrow[srow] * corr + sum;
                mrow[srow] = mx;
            }
        }
        __syncthreads();

        // ---- Rescale accumulators ----
#pragma unroll
        for (int mt = 0; mt < 4; mt++) {
            float c_lo = crow[mt * 16 + g];
            float c_hi = crow[mt * 16 + 8 + g];
#pragma unroll
            for (int nt = 0; nt < 8; nt++) {
                oacc[mt][nt][0] *= c_lo; oacc[mt][nt][1] *= c_lo;
                oacc[mt][nt][2] *= c_hi; oacc[mt][nt][3] *= c_hi;
            }
        }

        // ---- O += P @ V  (V B-frags direct from gmem/L2, kt+1 prefetch) ----
        {
            const float* vb = V + ((size_t)(kb * BN) + t) * FD + w * 64 + g;
            unsigned vreg[2][16];
#pragma unroll
            for (int nt = 0; nt < 8; nt++) {
                vreg[0][2 * nt]     = fu(vb[nt * 8]);            // key +t
                vreg[0][2 * nt + 1] = fu(vb[4 * FD + nt * 8]);   // key +t+4
            }
#pragma unroll
            for (int kt = 0; kt < 8; kt++) {
                const int cur = kt & 1;
                if (kt < 7) {
                    const float* vn = vb + (kt + 1) * 8 * FD;
#pragma unroll
                    for (int nt = 0; nt < 8; nt++) {
                        vreg[cur ^ 1][2 * nt]     = fu(vn[nt * 8]);
                        vreg[cur ^ 1][2 * nt + 1] = fu(vn[4 * FD + nt * 8]);
                    }
                }
                unsigned afr[4][4];
#pragma unroll
                for (int mt = 0; mt < 4; mt++)
                    ldsm_x4(afr[mt],
                            ss_b + 4u * ((mt * 16 + a_r) * SS + kt * 8 + a_c));
#pragma unroll
                for (int nt = 0; nt < 8; nt++)
#pragma unroll
                    for (int mt = 0; mt < 4; mt++)
                        mma8(oacc[mt][nt], afr[mt], &vreg[cur][2 * nt]);
            }
        }
    }

    // ---- Epilogue ----
#pragma unroll
    for (int mt = 0; mt < 4; mt++) {
        float inv_lo = 1.f / lrow[mt * 16 + g];
        float inv_hi = 1.f / lrow[mt * 16 + 8 + g];
#pragma unroll
        for (int nt = 0; nt < 8; nt++) {
            int col = w * 64 + nt * 8 + 2 * t;
            *(float2*)(O + (size_t)(qb * BM + mt * 16 + g) * FD + col) =
                make_float2(oacc[mt][nt][0] * inv_lo, oacc[mt][nt][1] * inv_lo);
            *(float2*)(O + (size_t)(qb * BM + mt * 16 + 8 + g) * FD + col) =
                make_float2(oacc[mt][nt][2] * inv_hi, oacc[mt][nt][3] * inv_hi);
        }
    }
}

// ---------------------------------------------------------------------------
// kernel_launch
// ---------------------------------------------------------------------------
extern "C" void kernel_launch(void* const* d_in, const int* in_sizes, int n_in,
                              void* d_out, int out_size)
{
    const float* x  = (const float*)d_in[0];
    const float* Wq = (const float*)d_in[1];
    const float* bq = (const float*)d_in[2];
    const float* Wk = (const float*)d_in[3];
    const float* bk = (const float*)d_in[4];
    const float* Wv = (const float*)d_in[5];
    const float* bv = (const float*)d_in[6];
    const float* Wo = (const float*)d_in[7];
    const float* bo = (const float*)d_in[8];
    float* out = (float*)d_out;

    float *pQ, *pK, *pV, *pA;
    cudaGetSymbolAddress((void**)&pQ, g_Q);
    cudaGetSymbolAddress((void**)&pK, g_K);
    cudaGetSymbolAddress((void**)&pV, g_V);
    cudaGetSymbolAddress((void**)&pA, g_att);

    const size_t FLASH_SMEM =
        (size_t)(BM * QS + BN * KS + BM * SS + 3 * BM) * sizeof(float);
    cudaFuncSetAttribute(flash_kernel,
                         cudaFuncAttributeMaxDynamicSharedMemorySize,
                         (int)FLASH_SMEM);

    dim3 blk(256);
    gemm_tf32_kernel<<<dim3(1, 128), blk>>>(x, Wq, bq, pQ, FD, MD);
    gemm_tf32_kernel<<<dim3(1, 128), blk>>>(x, Wk, bk, pK, FD, MD);
    gemm_tf32_kernel<<<dim3(4, 128), blk>>>(x, Wv, bv, pV, FD, FD);
    flash_kernel<<<NPTS / BM, 256, FLASH_SMEM>>>(pQ, pK, pV, pA);
    gemm_tf32_kernel<<<dim3(4, 128), blk>>>(pA, Wo, bo, out, FD, FD);
}

// round 7
// speedup vs baseline: 5.2839x; 1.9294x over previous
#include <cuda_runtime.h>
#include <cuda_bf16.h>
#include <cstdint>

#define NPTS 16384
#define FD   512
#define MD   128
#define BM   64
#define BN   64
#define NKV  (NPTS / BN)

// bf16-element strides; (stride*2/16) odd => ldmatrix conflict-free
#define QSB 136   // 272B rows (17x16)
#define KSB 136
#define VSB 520   // 1040B rows (65x16)
#define SSF 68    // f32 score stride (272B)
#define PSB 72    // 144B rows (9x16)

// smem byte offsets (all 16B aligned)
#define OFF_Q   0
#define OFF_K   17408              // 2 buffers x 17408
#define OFF_V   52224              // 2 buffers x 66560
#define OFF_S   185344             // f32 scores 17408
#define OFF_P   202752             // bf16 P 9216
#define OFF_M   211968
#define OFF_L   212224
#define OFF_C   212480
#define SMEM_TOTAL 212736
#define KBUF 17408
#define VBUF 66560

// Scratch (device globals: allocation-free rule)
__device__ __nv_bfloat16 g_Qb[NPTS * MD];
__device__ __nv_bfloat16 g_Kb[NPTS * MD];
__device__ __nv_bfloat16 g_Vb[NPTS * FD];
__device__ float g_att[NPTS * FD];

// ---------------------------------------------------------------------------
// helpers
// ---------------------------------------------------------------------------
__device__ __forceinline__ float cvt_tf32(float x) {
    unsigned u;
    asm("cvt.rna.tf32.f32 %0, %1;" : "=r"(u) : "f"(x));
    return __uint_as_float(u);
}
__device__ __forceinline__ unsigned fu(float x) { return __float_as_uint(x); }

__device__ __forceinline__ void ldsm4(unsigned* r, uint32_t a) {
    asm volatile("ldmatrix.sync.aligned.m8n8.x4.shared.b16 {%0,%1,%2,%3}, [%4];"
                 : "=r"(r[0]), "=r"(r[1]), "=r"(r[2]), "=r"(r[3]) : "r"(a));
}
__device__ __forceinline__ void ldsm2(unsigned* r, uint32_t a) {
    asm volatile("ldmatrix.sync.aligned.m8n8.x2.shared.b16 {%0,%1}, [%2];"
                 : "=r"(r[0]), "=r"(r[1]) : "r"(a));
}
__device__ __forceinline__ void ldsm2t(unsigned* r, uint32_t a) {
    asm volatile("ldmatrix.sync.aligned.m8n8.x2.trans.shared.b16 {%0,%1}, [%2];"
                 : "=r"(r[0]), "=r"(r[1]) : "r"(a));
}

// bf16 m16n8k16, fp32 accum
__device__ __forceinline__ void mma16(float* d, const unsigned* a, const unsigned* b) {
    asm volatile(
        "mma.sync.aligned.m16n8k16.row.col.f32.bf16.bf16.f32 "
        "{%0,%1,%2,%3}, {%4,%5,%6,%7}, {%8,%9}, {%0,%1,%2,%3};"
        : "+f"(d[0]), "+f"(d[1]), "+f"(d[2]), "+f"(d[3])
        : "r"(a[0]), "r"(a[1]), "r"(a[2]), "r"(a[3]), "r"(b[0]), "r"(b[1]));
}
// tf32 m16n8k8 (projection GEMMs)
__device__ __forceinline__ void mma8(float* d, const unsigned* a, const unsigned* b) {
    asm volatile(
        "mma.sync.aligned.m16n8k8.row.col.f32.tf32.tf32.f32 "
        "{%0,%1,%2,%3}, {%4,%5,%6,%7}, {%8,%9}, {%0,%1,%2,%3};"
        : "+f"(d[0]), "+f"(d[1]), "+f"(d[2]), "+f"(d[3])
        : "r"(a[0]), "r"(a[1]), "r"(a[2]), "r"(a[3]), "r"(b[0]), "r"(b[1]));
}

__device__ __forceinline__ void cpa16(uint32_t dst, const void* src) {
    asm volatile("cp.async.cg.shared.global [%0], [%1], 16;" :: "r"(dst), "l"(src));
}
__device__ __forceinline__ void cp_commit() {
    asm volatile("cp.async.commit_group;");
}
__device__ __forceinline__ void cp_wait0() {
    asm volatile("cp.async.wait_group 0;");
}

// ---------------------------------------------------------------------------
// TF32 GEMM: C[128x128 tile] = A @ B + bias. OUT_BF16 selects output type.
// ---------------------------------------------------------------------------
#define AS_STRIDE 36
#define BS_STRIDE 136
template <int OUT_BF16>
__global__ __launch_bounds__(256) void gemm_tf32_kernel(
    const float* __restrict__ A, const float* __restrict__ B,
    const float* __restrict__ bias, void* __restrict__ Cv,
    int Kd, int Nc)
{
    __shared__ float As[128 * AS_STRIDE];
    __shared__ float Bs[32 * BS_STRIDE];

    const int tid  = threadIdx.x;
    const int w    = tid >> 5;
    const int lane = tid & 31;
    const int g    = lane >> 2;
    const int t    = lane & 3;
    const int wm   = w & 3;
    const int wn   = w >> 2;
    const int rowBase = blockIdx.y * 128;
    const int colBase = blockIdx.x * 128;

    float acc[2][8][4];
#pragma unroll
    for (int mt = 0; mt < 2; mt++)
#pragma unroll
        for (int nt = 0; nt < 8; nt++)
#pragma unroll
            for (int e = 0; e < 4; e++) acc[mt][nt][e] = 0.f;

    for (int k0 = 0; k0 < Kd; k0 += 32) {
        float4 areg[4], breg[4];
#pragma unroll
        for (int e = 0; e < 4; e++) {
            int f4 = tid + 256 * e;
            int ar = f4 >> 3, ac4 = f4 & 7;
            areg[e] = *(const float4*)(A + (size_t)(rowBase + ar) * Kd + k0 + ac4 * 4);
            int br = f4 >> 5, bc4 = f4 & 31;
            breg[e] = *(const float4*)(B + (size_t)(k0 + br) * Nc + colBase + bc4 * 4);
        }
        __syncthreads();
#pragma unroll
        for (int e = 0; e < 4; e++) {
            int f4 = tid + 256 * e;
            int ar = f4 >> 3, ac4 = f4 & 7;
            float4 v = areg[e];
            v.x = cvt_tf32(v.x); v.y = cvt_tf32(v.y);
            v.z = cvt_tf32(v.z); v.w = cvt_tf32(v.w);
            *(float4*)(As + ar * AS_STRIDE + ac4 * 4) = v;
            int br = f4 >> 5, bc4 = f4 & 31;
            float4 u = breg[e];
            u.x = cvt_tf32(u.x); u.y = cvt_tf32(u.y);
            u.z = cvt_tf32(u.z); u.w = cvt_tf32(u.w);
            *(float4*)(Bs + br * BS_STRIDE + bc4 * 4) = u;
        }
        __syncthreads();

#pragma unroll
        for (int kt = 0; kt < 4; kt++) {
            unsigned afr[2][4];
#pragma unroll
            for (int mt = 0; mt < 2; mt++) {
                const float* ap = As + (wm * 32 + mt * 16) * AS_STRIDE + kt * 8;
                afr[mt][0] = fu(ap[g * AS_STRIDE + t]);
                afr[mt][1] = fu(ap[(g + 8) * AS_STRIDE + t]);
                afr[mt][2] = fu(ap[g * AS_STRIDE + t + 4]);
                afr[mt][3] = fu(ap[(g + 8) * AS_STRIDE + t + 4]);
            }
#pragma unroll
            for (int nt = 0; nt < 8; nt++) {
                const float* bp = Bs + wn * 64 + nt * 8;
                unsigned bfr[2];
                bfr[0] = fu(bp[(kt * 8 + t) * BS_STRIDE + g]);
                bfr[1] = fu(bp[(kt * 8 + t + 4) * BS_STRIDE + g]);
#pragma unroll
                for (int mt = 0; mt < 2; mt++) mma8(acc[mt][nt], afr[mt], bfr);
            }
        }
    }

#pragma unroll
    for (int mt = 0; mt < 2; mt++) {
        int r0 = rowBase + wm * 32 + mt * 16;
#pragma unroll
        for (int nt = 0; nt < 8; nt++) {
            int col = colBase + wn * 64 + nt * 8 + 2 * t;
            float b0 = bias[col], b1 = bias[col + 1];
            if (OUT_BF16) {
                __nv_bfloat16* C = (__nv_bfloat16*)Cv;
                __nv_bfloat162 lo = __float22bfloat162_rn(
                    make_float2(acc[mt][nt][0] + b0, acc[mt][nt][1] + b1));
                __nv_bfloat162 hi = __float22bfloat162_rn(
                    make_float2(acc[mt][nt][2] + b0, acc[mt][nt][3] + b1));
                *(__nv_bfloat162*)(C + (size_t)(r0 + g)     * Nc + col) = lo;
                *(__nv_bfloat162*)(C + (size_t)(r0 + g + 8) * Nc + col) = hi;
            } else {
                float* C = (float*)Cv;
                *(float2*)(C + (size_t)(r0 + g) * Nc + col) =
                    make_float2(acc[mt][nt][0] + b0, acc[mt][nt][1] + b1);
                *(float2*)(C + (size_t)(r0 + g + 8) * Nc + col) =
                    make_float2(acc[mt][nt][2] + b0, acc[mt][nt][3] + b1);
            }
        }
    }
}

// ---------------------------------------------------------------------------
// Flash attention v3: bf16 m16n8k16, cp.async double-buffered K/V,
// ldmatrix everywhere (V via ldmatrix.trans).
// ---------------------------------------------------------------------------
__global__ __launch_bounds__(256, 1) void flash_kernel(
    const __nv_bfloat16* __restrict__ Q, const __nv_bfloat16* __restrict__ K,
    const __nv_bfloat16* __restrict__ V, float* __restrict__ O)
{
    extern __shared__ char sm[];
    float* Ssf  = (float*)(sm + OFF_S);
    __nv_bfloat16* Ps = (__nv_bfloat16*)(sm + OFF_P);
    float* mrow = (float*)(sm + OFF_M);
    float* lrow = (float*)(sm + OFF_L);
    float* crow = (float*)(sm + OFF_C);

    const uint32_t smem_u = (uint32_t)__cvta_generic_to_shared(sm);
    const uint32_t qs_u = smem_u + OFF_Q;
    const uint32_t ks_u = smem_u + OFF_K;
    const uint32_t vs_u = smem_u + OFF_V;
    const uint32_t ps_u = smem_u + OFF_P;

    const int tid  = threadIdx.x;
    const int w    = tid >> 5;
    const int lane = tid & 31;
    const int g    = lane >> 2;
    const int t    = lane & 3;
    const int wm   = w & 1;
    const int wn   = w >> 1;
    const int qb   = blockIdx.x;

    // ldmatrix lane geometry
    const int a_r  = lane & 15;                       // A-frag row
    const int a_cB = (lane >> 4) * 16;                // A-frag 16B col half
    const int b_r  = lane & 7;                        // B-frag row
    const int b_hi = (lane >> 3) & 1;                 // B-frag k/row +8 half

    // ---- preloop: stage Q + (K,V) block 0 via cp.async ----
    {
        const int r = tid >> 2, s = tid & 3;
        const char* gq = (const char*)(Q + (size_t)(qb * BM + r) * MD + s * 32);
        const char* gk = (const char*)(K + (size_t)(0 * BN + r) * MD + s * 32);
#pragma unroll
        for (int e = 0; e < 4; e++) {
            cpa16(qs_u + r * 272 + s * 64 + 16 * e, gq + 16 * e);
            cpa16(ks_u + r * 272 + s * 64 + 16 * e, gk + 16 * e);
        }
#pragma unroll
        for (int e = 0; e < 16; e++) {
            int f = tid + 256 * e;
            int vr = f >> 6, vc = f & 63;     // 64 x 16B segs per 512-bf16 row
            cpa16(vs_u + vr * 1040 + vc * 16,
                  (const char*)(V + (size_t)vr * FD) + vc * 16);
        }
        cp_commit();
    }
    if (tid < BM) { mrow[tid] = -1e30f; lrow[tid] = 0.f; }

    float oacc[4][8][4];
#pragma unroll
    for (int mt = 0; mt < 4; mt++)
#pragma unroll
        for (int nt = 0; nt < 8; nt++)
#pragma unroll
            for (int e = 0; e < 4; e++) oacc[mt][nt][e] = 0.f;

    const float scale = 0.08838834764831845f;   // 1/sqrt(128)

    for (int kb = 0; kb < NKV; kb++) {
        const int cur = kb & 1;
        cp_wait0();
        __syncthreads();   // S1: buf[cur] ready everywhere; prev PV reads done

        // stage next block into buf[cur^1]
        if (kb + 1 < NKV) {
            const int r = tid >> 2, s = tid & 3;
            const uint32_t kd = ks_u + (cur ^ 1) * KBUF;
            const uint32_t vd = vs_u + (cur ^ 1) * VBUF;
            const char* gk = (const char*)(K + (size_t)((kb + 1) * BN + r) * MD + s * 32);
#pragma unroll
            for (int e = 0; e < 4; e++)
                cpa16(kd + r * 272 + s * 64 + 16 * e, gk + 16 * e);
#pragma unroll
            for (int e = 0; e < 16; e++) {
                int f = tid + 256 * e;
                int vr = f >> 6, vc = f & 63;
                cpa16(vd + vr * 1040 + vc * 16,
                      (const char*)(V + (size_t)((kb + 1) * BN + vr) * FD) + vc * 16);
            }
            cp_commit();
        }

        // ---- S = Q @ K^T (bf16 m16n8k16) ----
        const uint32_t ksm = ks_u + cur * KBUF;
        float sacc[2][2][4];
#pragma unroll
        for (int mt = 0; mt < 2; mt++)
#pragma unroll
            for (int nt = 0; nt < 2; nt++)
#pragma unroll
                for (int e = 0; e < 4; e++) sacc[mt][nt][e] = 0.f;

#pragma unroll
        for (int kt = 0; kt < 8; kt++) {
            unsigned aq[2][4];
#pragma unroll
            for (int mt = 0; mt < 2; mt++)
                ldsm4(aq[mt], qs_u + (wm * 32 + mt * 16 + a_r) * 272 + kt * 32 + a_cB);
#pragma unroll
            for (int nt = 0; nt < 2; nt++) {
                unsigned bk[2];
                ldsm2(bk, ksm + (wn * 16 + nt * 8 + b_r) * 272 + kt * 32 + b_hi * 16);
                mma16(sacc[0][nt], aq[0], bk);
                mma16(sacc[1][nt], aq[1], bk);
            }
        }
#pragma unroll
        for (int mt = 0; mt < 2; mt++) {
            int r0 = wm * 32 + mt * 16;
#pragma unroll
            for (int nt = 0; nt < 2; nt++) {
                int c0 = wn * 16 + nt * 8 + 2 * t;
                *(float2*)(Ssf + (r0 + g) * SSF + c0) =
                    make_float2(sacc[mt][nt][0] * scale, sacc[mt][nt][1] * scale);
                *(float2*)(Ssf + (r0 + g + 8) * SSF + c0) =
                    make_float2(sacc[mt][nt][2] * scale, sacc[mt][nt][3] * scale);
            }
        }
        __syncthreads();   // S2

        // ---- Online softmax: 4 threads/row, cols {2sq+8j, +1}, P -> bf16 ----
        {
            const int srow = tid >> 2;
            const int sq   = tid & 3;
            const float* rowp = Ssf + srow * SSF;
            float2 v[8];
            float m_old = mrow[srow];
            float mx = m_old;
#pragma unroll
            for (int j = 0; j < 8; j++) {
                v[j] = *(const float2*)(rowp + 2 * sq + 8 * j);
                mx = fmaxf(mx, fmaxf(v[j].x, v[j].y));
            }
            mx = fmaxf(mx, __shfl_xor_sync(0xffffffffu, mx, 1));
            mx = fmaxf(mx, __shfl_xor_sync(0xffffffffu, mx, 2));
            float sum = 0.f;
#pragma unroll
            for (int j = 0; j < 8; j++) {
                float p0 = __expf(v[j].x - mx);
                float p1 = __expf(v[j].y - mx);
                sum += p0 + p1;
                *(__nv_bfloat162*)(Ps + srow * PSB + 2 * sq + 8 * j) =
                    __float22bfloat162_rn(make_float2(p0, p1));
            }
            sum += __shfl_xor_sync(0xffffffffu, sum, 1);
            sum += __shfl_xor_sync(0xffffffffu, sum, 2);
            if (sq == 0) {
                float corr = __expf(m_old - mx);
                crow[srow] = corr;
                lrow[srow] = lrow[srow] * corr + sum;
                mrow[srow] = mx;
            }
        }
        __syncthreads();   // S3

        // ---- Rescale accumulators ----
#pragma unroll
        for (int mt = 0; mt < 4; mt++) {
            float c_lo = crow[mt * 16 + g];
            float c_hi = crow[mt * 16 + 8 + g];
#pragma unroll
            for (int nt = 0; nt < 8; nt++) {
                oacc[mt][nt][0] *= c_lo; oacc[mt][nt][1] *= c_lo;
                oacc[mt][nt][2] *= c_hi; oacc[mt][nt][3] *= c_hi;
            }
        }

        // ---- O += P @ V (P A-frag ldsm4; V B-frag ldsm2.trans) ----
        const uint32_t vsm = vs_u + cur * VBUF;
#pragma unroll
        for (int kt = 0; kt < 4; kt++) {
            unsigned ap[4][4];
#pragma unroll
            for (int mt = 0; mt < 4; mt++)
                ldsm4(ap[mt], ps_u + (mt * 16 + a_r) * 144 + kt * 32 + a_cB);
#pragma unroll
            for (int nt = 0; nt < 8; nt++) {
                unsigned bv[2];
                ldsm2t(bv, vsm + (kt * 16 + b_r + b_hi * 8) * 1040
                               + (w * 64 + nt * 8) * 2);
#pragma unroll
                for (int mt = 0; mt < 4; mt++)
                    mma16(oacc[mt][nt], ap[mt], bv);
            }
        }
    }

    // ---- Epilogue ----
#pragma unroll
    for (int mt = 0; mt < 4; mt++) {
        float inv_lo = 1.f / lrow[mt * 16 + g];
        float inv_hi = 1.f / lrow[mt * 16 + 8 + g];
#pragma unroll
        for (int nt = 0; nt < 8; nt++) {
            int col = w * 64 + nt * 8 + 2 * t;
            *(float2*)(O + (size_t)(qb * BM + mt * 16 + g) * FD + col) =
                make_float2(oacc[mt][nt][0] * inv_lo, oacc[mt][nt][1] * inv_lo);
            *(float2*)(O + (size_t)(qb * BM + mt * 16 + 8 + g) * FD + col) =
                make_float2(oacc[mt][nt][2] * inv_hi, oacc[mt][nt][3] * inv_hi);
        }
    }
}

// ---------------------------------------------------------------------------
// kernel_launch
// ---------------------------------------------------------------------------
extern "C" void kernel_launch(void* const* d_in, const int* in_sizes, int n_in,
                              void* d_out, int out_size)
{
    const float* x  = (const float*)d_in[0];
    const float* Wq = (const float*)d_in[1];
    const float* bq = (const float*)d_in[2];
    const float* Wk = (const float*)d_in[3];
    const float* bk = (const float*)d_in[4];
    const float* Wv = (const float*)d_in[5];
    const float* bv = (const float*)d_in[6];
    const float* Wo = (const float*)d_in[7];
    const float* bo = (const float*)d_in[8];
    float* out = (float*)d_out;

    __nv_bfloat16 *pQ, *pK, *pV;
    float* pA;
    cudaGetSymbolAddress((void**)&pQ, g_Qb);
    cudaGetSymbolAddress((void**)&pK, g_Kb);
    cudaGetSymbolAddress((void**)&pV, g_Vb);
    cudaGetSymbolAddress((void**)&pA, g_att);

    cudaFuncSetAttribute(flash_kernel,
                         cudaFuncAttributeMaxDynamicSharedMemorySize, SMEM_TOTAL);

    dim3 blk(256);
    gemm_tf32_kernel<1><<<dim3(1, 128), blk>>>(x, Wq, bq, pQ, FD, MD);
    gemm_tf32_kernel<1><<<dim3(1, 128), blk>>>(x, Wk, bk, pK, FD, MD);
    gemm_tf32_kernel<1><<<dim3(4, 128), blk>>>(x, Wv, bv, pV, FD, FD);
    flash_kernel<<<NPTS / BM, 256, SMEM_TOTAL>>>(pQ, pK, pV, pA);
    gemm_tf32_kernel<0><<<dim3(4, 128), blk>>>(pA, Wo, bo, out, FD, FD);
}

// round 8
// speedup vs baseline: 5.5370x; 1.0479x over previous
#include <cuda_runtime.h>
#include <cuda_bf16.h>
#include <cstdint>

#define NPTS 16384
#define FD   512
#define MD   128
#define BM   64
#define BN   64
#define NKV  (NPTS / BN)

// smem byte offsets (all 16B aligned)
#define OFF_Q   0                  // 64 rows x 272B
#define OFF_K   17408              // 2 buffers x 17408
#define OFF_V   52224              // 2 buffers x 66560
#define OFF_P   185344             // 4 pairs x (16 rows x 144B) = 9216
#define OFF_MP  194560             // 4 pairs x 32 floats = 512
#define OFF_SP  195072             // 4 pairs x 32 floats = 512
#define SMEM_TOTAL 195584
#define KBUF 17408
#define VBUF 66560

// Scratch (device globals: allocation-free rule)
__device__ __nv_bfloat16 g_Qb[NPTS * MD];
__device__ __nv_bfloat16 g_Kb[NPTS * MD];
__device__ __nv_bfloat16 g_Vb[NPTS * FD];
__device__ float g_att[NPTS * FD];

// ---------------------------------------------------------------------------
// helpers
// ---------------------------------------------------------------------------
__device__ __forceinline__ float cvt_tf32(float x) {
    unsigned u;
    asm("cvt.rna.tf32.f32 %0, %1;" : "=r"(u) : "f"(x));
    return __uint_as_float(u);
}
__device__ __forceinline__ unsigned fu(float x) { return __float_as_uint(x); }

__device__ __forceinline__ void ldsm4(unsigned* r, uint32_t a) {
    asm volatile("ldmatrix.sync.aligned.m8n8.x4.shared.b16 {%0,%1,%2,%3}, [%4];"
                 : "=r"(r[0]), "=r"(r[1]), "=r"(r[2]), "=r"(r[3]) : "r"(a));
}
__device__ __forceinline__ void ldsm4t(unsigned* r, uint32_t a) {
    asm volatile("ldmatrix.sync.aligned.m8n8.x4.trans.shared.b16 {%0,%1,%2,%3}, [%4];"
                 : "=r"(r[0]), "=r"(r[1]), "=r"(r[2]), "=r"(r[3]) : "r"(a));
}

// bf16 m16n8k16, fp32 accum
__device__ __forceinline__ void mma16(float* d, const unsigned* a, const unsigned* b) {
    asm volatile(
        "mma.sync.aligned.m16n8k16.row.col.f32.bf16.bf16.f32 "
        "{%0,%1,%2,%3}, {%4,%5,%6,%7}, {%8,%9}, {%0,%1,%2,%3};"
        : "+f"(d[0]), "+f"(d[1]), "+f"(d[2]), "+f"(d[3])
        : "r"(a[0]), "r"(a[1]), "r"(a[2]), "r"(a[3]), "r"(b[0]), "r"(b[1]));
}
// tf32 m16n8k8 (projection GEMMs)
__device__ __forceinline__ void mma8(float* d, const unsigned* a, const unsigned* b) {
    asm volatile(
        "mma.sync.aligned.m16n8k8.row.col.f32.tf32.tf32.f32 "
        "{%0,%1,%2,%3}, {%4,%5,%6,%7}, {%8,%9}, {%0,%1,%2,%3};"
        : "+f"(d[0]), "+f"(d[1]), "+f"(d[2]), "+f"(d[3])
        : "r"(a[0]), "r"(a[1]), "r"(a[2]), "r"(a[3]), "r"(b[0]), "r"(b[1]));
}

__device__ __forceinline__ void cpa16(uint32_t dst, const void* src) {
    asm volatile("cp.async.cg.shared.global [%0], [%1], 16;" :: "r"(dst), "l"(src));
}
__device__ __forceinline__ void cp_commit() {
    asm volatile("cp.async.commit_group;");
}
__device__ __forceinline__ void cp_wait0() {
    asm volatile("cp.async.wait_group 0;");
}
__device__ __forceinline__ void pair_bar(int id) {
    asm volatile("bar.sync %0, 64;" :: "r"(id) : "memory");
}

// ---------------------------------------------------------------------------
// TF32 GEMM: C[128x128 tile] = A @ B + bias. OUT_BF16 selects output type.
// ---------------------------------------------------------------------------
#define AS_STRIDE 36
#define BS_STRIDE 136
template <int OUT_BF16>
__global__ __launch_bounds__(256) void gemm_tf32_kernel(
    const float* __restrict__ A, const float* __restrict__ B,
    const float* __restrict__ bias, void* __restrict__ Cv,
    int Kd, int Nc)
{
    __shared__ float As[128 * AS_STRIDE];
    __shared__ float Bs[32 * BS_STRIDE];

    const int tid  = threadIdx.x;
    const int w    = tid >> 5;
    const int lane = tid & 31;
    const int g    = lane >> 2;
    const int t    = lane & 3;
    const int wm   = w & 3;
    const int wn   = w >> 2;
    const int rowBase = blockIdx.y * 128;
    const int colBase = blockIdx.x * 128;

    float acc[2][8][4];
#pragma unroll
    for (int mt = 0; mt < 2; mt++)
#pragma unroll
        for (int nt = 0; nt < 8; nt++)
#pragma unroll
            for (int e = 0; e < 4; e++) acc[mt][nt][e] = 0.f;

    for (int k0 = 0; k0 < Kd; k0 += 32) {
        float4 areg[4], breg[4];
#pragma unroll
        for (int e = 0; e < 4; e++) {
            int f4 = tid + 256 * e;
            int ar = f4 >> 3, ac4 = f4 & 7;
            areg[e] = *(const float4*)(A + (size_t)(rowBase + ar) * Kd + k0 + ac4 * 4);
            int br = f4 >> 5, bc4 = f4 & 31;
            breg[e] = *(const float4*)(B + (size_t)(k0 + br) * Nc + colBase + bc4 * 4);
        }
        __syncthreads();
#pragma unroll
        for (int e = 0; e < 4; e++) {
            int f4 = tid + 256 * e;
            int ar = f4 >> 3, ac4 = f4 & 7;
            float4 v = areg[e];
            v.x = cvt_tf32(v.x); v.y = cvt_tf32(v.y);
            v.z = cvt_tf32(v.z); v.w = cvt_tf32(v.w);
            *(float4*)(As + ar * AS_STRIDE + ac4 * 4) = v;
            int br = f4 >> 5, bc4 = f4 & 31;
            float4 u = breg[e];
            u.x = cvt_tf32(u.x); u.y = cvt_tf32(u.y);
            u.z = cvt_tf32(u.z); u.w = cvt_tf32(u.w);
            *(float4*)(Bs + br * BS_STRIDE + bc4 * 4) = u;
        }
        __syncthreads();

#pragma unroll
        for (int kt = 0; kt < 4; kt++) {
            unsigned afr[2][4];
#pragma unroll
            for (int mt = 0; mt < 2; mt++) {
                const float* ap = As + (wm * 32 + mt * 16) * AS_STRIDE + kt * 8;
                afr[mt][0] = fu(ap[g * AS_STRIDE + t]);
                afr[mt][1] = fu(ap[(g + 8) * AS_STRIDE + t]);
                afr[mt][2] = fu(ap[g * AS_STRIDE + t + 4]);
                afr[mt][3] = fu(ap[(g + 8) * AS_STRIDE + t + 4]);
            }
#pragma unroll
            for (int nt = 0; nt < 8; nt++) {
                const float* bp = Bs + wn * 64 + nt * 8;
                unsigned bfr[2];
                bfr[0] = fu(bp[(kt * 8 + t) * BS_STRIDE + g]);
                bfr[1] = fu(bp[(kt * 8 + t + 4) * BS_STRIDE + g]);
#pragma unroll
                for (int mt = 0; mt < 2; mt++) mma8(acc[mt][nt], afr[mt], bfr);
            }
        }
    }

#pragma unroll
    for (int mt = 0; mt < 2; mt++) {
        int r0 = rowBase + wm * 32 + mt * 16;
#pragma unroll
        for (int nt = 0; nt < 8; nt++) {
            int col = colBase + wn * 64 + nt * 8 + 2 * t;
            float b0 = bias[col], b1 = bias[col + 1];
            if (OUT_BF16) {
                __nv_bfloat16* C = (__nv_bfloat16*)Cv;
                __nv_bfloat162 lo = __float22bfloat162_rn(
                    make_float2(acc[mt][nt][0] + b0, acc[mt][nt][1] + b1));
                __nv_bfloat162 hi = __float22bfloat162_rn(
                    make_float2(acc[mt][nt][2] + b0, acc[mt][nt][3] + b1));
                *(__nv_bfloat162*)(C + (size_t)(r0 + g)     * Nc + col) = lo;
                *(__nv_bfloat162*)(C + (size_t)(r0 + g + 8) * Nc + col) = hi;
            } else {
                float* C = (float*)Cv;
                *(float2*)(C + (size_t)(r0 + g) * Nc + col) =
                    make_float2(acc[mt][nt][0] + b0, acc[mt][nt][1] + b1);
                *(float2*)(C + (size_t)(r0 + g + 8) * Nc + col) =
                    make_float2(acc[mt][nt][2] + b0, acc[mt][nt][3] + b1);
            }
        }
    }
}

// ---------------------------------------------------------------------------
// Flash attention v4: warp-pair decoupled. Pair p owns rows p*16..p*16+16.
// Warp (p, s): S-phase computes S[16 x 32] (cols s*32..), softmax on register
// fragments (cross-half exchange via 64-thread named barrier), PV-phase
// computes O[16 x 256] (feats s*256..). One CTA sync/iter (K/V buffers).
// ---------------------------------------------------------------------------
__global__ __launch_bounds__(256, 1) void flash_kernel(
    const __nv_bfloat16* __restrict__ Q, const __nv_bfloat16* __restrict__ K,
    const __nv_bfloat16* __restrict__ V, float* __restrict__ O)
{
    extern __shared__ char sm[];
    const uint32_t smem_u = (uint32_t)__cvta_generic_to_shared(sm);
    const uint32_t qs_u = smem_u + OFF_Q;
    const uint32_t ks_u = smem_u + OFF_K;
    const uint32_t vs_u = smem_u + OFF_V;

    const int tid  = threadIdx.x;
    const int w    = tid >> 5;
    const int lane = tid & 31;
    const int g    = lane >> 2;
    const int t    = lane & 3;
    const int p    = w >> 1;       // pair 0..3
    const int s    = w & 1;        // half 0..1
    const int qb   = blockIdx.x;
    const int barid = p + 1;

    const uint32_t pp_u = smem_u + OFF_P + p * 2304;
    __nv_bfloat16* Pp = (__nv_bfloat16*)(sm + OFF_P + p * 2304);
    float* mpart = (float*)(sm + OFF_MP + p * 128);
    float* spart = (float*)(sm + OFF_SP + p * 128);

    // ldmatrix lane geometry
    const int a_r   = lane & 15;                         // A-frag row
    const int a_cB  = (lane >> 4) * 16;                  // A-frag 16B col half
    const int k_row = ((lane >> 4) & 1) * 8 + (lane & 7);// K x4: 2 B-frags
    const int k_cB  = ((lane >> 3) & 1) * 16;
    const int v_row = (lane & 7) + ((lane >> 3) & 1) * 8;// V x4 trans: 2 B-frags
    const int v_f   = (lane >> 4) * 8;

    // ---- preloop: stage Q + (K,V) block 0 via cp.async ----
    {
        const int r = tid >> 2, s4 = tid & 3;
        const char* gq = (const char*)(Q + (size_t)(qb * BM + r) * MD + s4 * 32);
        const char* gk = (const char*)(K + (size_t)r * MD + s4 * 32);
#pragma unroll
        for (int e = 0; e < 4; e++) {
            cpa16(qs_u + r * 272 + s4 * 64 + 16 * e, gq + 16 * e);
            cpa16(ks_u + r * 272 + s4 * 64 + 16 * e, gk + 16 * e);
        }
#pragma unroll
        for (int e = 0; e < 16; e++) {
            int f = tid + 256 * e;
            int vr = f >> 6, vc = f & 63;
            cpa16(vs_u + vr * 1040 + vc * 16,
                  (const char*)(V + (size_t)vr * FD) + vc * 16);
        }
        cp_commit();
    }

    float oacc[32][4];
#pragma unroll
    for (int j = 0; j < 32; j++)
#pragma unroll
        for (int e = 0; e < 4; e++) oacc[j][e] = 0.f;

    float m_lo = -1e30f, m_hi = -1e30f, l_lo = 0.f, l_hi = 0.f;
    const float scale = 0.08838834764831845f;   // 1/sqrt(128)

    for (int kb = 0; kb < NKV; kb++) {
        const int cur = kb & 1;
        cp_wait0();
        __syncthreads();   // buf[cur] ready; prev-iter V/K reads complete

        if (kb + 1 < NKV) {
            const int r = tid >> 2, s4 = tid & 3;
            const uint32_t kd = ks_u + (cur ^ 1) * KBUF;
            const uint32_t vd = vs_u + (cur ^ 1) * VBUF;
            const char* gk = (const char*)(K + (size_t)((kb + 1) * BN + r) * MD + s4 * 32);
#pragma unroll
            for (int e = 0; e < 4; e++)
                cpa16(kd + r * 272 + s4 * 64 + 16 * e, gk + 16 * e);
#pragma unroll
            for (int e = 0; e < 16; e++) {
                int f = tid + 256 * e;
                int vr = f >> 6, vc = f & 63;
                cpa16(vd + vr * 1040 + vc * 16,
                      (const char*)(V + (size_t)((kb + 1) * BN + vr) * FD) + vc * 16);
            }
            cp_commit();
        }

        // ---- S = Q @ K^T : warp computes rows p*16..+16, cols s*32..+32 ----
        const uint32_t ksm = ks_u + cur * KBUF;
        float sacc[4][4];
#pragma unroll
        for (int nt = 0; nt < 4; nt++)
#pragma unroll
            for (int e = 0; e < 4; e++) sacc[nt][e] = 0.f;

#pragma unroll
        for (int kt = 0; kt < 8; kt++) {
            unsigned aq[4];
            ldsm4(aq, qs_u + (p * 16 + a_r) * 272 + kt * 32 + a_cB);
#pragma unroll
            for (int n2 = 0; n2 < 2; n2++) {
                unsigned bk[4];
                ldsm4(bk, ksm + (s * 32 + n2 * 16 + k_row) * 272 + kt * 32 + k_cB);
                mma16(sacc[n2 * 2],     aq, bk);
                mma16(sacc[n2 * 2 + 1], aq, bk + 2);
            }
        }

        // ---- softmax on fragments ----
        float mlo = m_lo, mhi = m_hi;
#pragma unroll
        for (int nt = 0; nt < 4; nt++) {
            sacc[nt][0] *= scale; sacc[nt][1] *= scale;
            sacc[nt][2] *= scale; sacc[nt][3] *= scale;
            mlo = fmaxf(mlo, fmaxf(sacc[nt][0], sacc[nt][1]));
            mhi = fmaxf(mhi, fmaxf(sacc[nt][2], sacc[nt][3]));
        }
        mlo = fmaxf(mlo, __shfl_xor_sync(0xffffffffu, mlo, 1));
        mlo = fmaxf(mlo, __shfl_xor_sync(0xffffffffu, mlo, 2));
        mhi = fmaxf(mhi, __shfl_xor_sync(0xffffffffu, mhi, 1));
        mhi = fmaxf(mhi, __shfl_xor_sync(0xffffffffu, mhi, 2));
        if (t == 0) {
            mpart[s * 16 + g]     = mlo;
            mpart[s * 16 + 8 + g] = mhi;
        }
        pair_bar(barid);
        const float mxlo = fmaxf(mlo, mpart[(s ^ 1) * 16 + g]);
        const float mxhi = fmaxf(mhi, mpart[(s ^ 1) * 16 + 8 + g]);
        const float clo = __expf(m_lo - mxlo);
        const float chi = __expf(m_hi - mxhi);

        float slo = 0.f, shi = 0.f;
#pragma unroll
        for (int nt = 0; nt < 4; nt++) {
            float p0 = __expf(sacc[nt][0] - mxlo);
            float p1 = __expf(sacc[nt][1] - mxlo);
            float p2 = __expf(sacc[nt][2] - mxhi);
            float p3 = __expf(sacc[nt][3] - mxhi);
            slo += p0 + p1;
            shi += p2 + p3;
            const int c0 = s * 32 + nt * 8 + 2 * t;
            *(__nv_bfloat162*)(Pp + g * 72 + c0) =
                __float22bfloat162_rn(make_float2(p0, p1));
            *(__nv_bfloat162*)(Pp + (8 + g) * 72 + c0) =
                __float22bfloat162_rn(make_float2(p2, p3));
        }
        slo += __shfl_xor_sync(0xffffffffu, slo, 1);
        slo += __shfl_xor_sync(0xffffffffu, slo, 2);
        shi += __shfl_xor_sync(0xffffffffu, shi, 1);
        shi += __shfl_xor_sync(0xffffffffu, shi, 2);
        if (t == 0) {
            spart[s * 16 + g]     = slo;
            spart[s * 16 + 8 + g] = shi;
        }
        pair_bar(barid);
        l_lo = l_lo * clo + slo + spart[(s ^ 1) * 16 + g];
        l_hi = l_hi * chi + shi + spart[(s ^ 1) * 16 + 8 + g];
        m_lo = mxlo; m_hi = mxhi;

        // ---- rescale accumulators ----
#pragma unroll
        for (int j = 0; j < 32; j++) {
            oacc[j][0] *= clo; oacc[j][1] *= clo;
            oacc[j][2] *= chi; oacc[j][3] *= chi;
        }

        // ---- O += P @ V : rows p*16..+16, feats s*256..+256 ----
        const uint32_t vsm = vs_u + cur * VBUF;
#pragma unroll
        for (int kt = 0; kt < 4; kt++) {
            unsigned ap[4];
            ldsm4(ap, pp_u + a_r * 144 + kt * 32 + a_cB);
#pragma unroll
            for (int j = 0; j < 16; j++) {
                unsigned bv[4];
                ldsm4t(bv, vsm + (kt * 16 + v_row) * 1040
                               + (s * 256 + j * 16 + v_f) * 2);
                mma16(oacc[2 * j],     ap, bv);
                mma16(oacc[2 * j + 1], ap, bv + 2);
            }
        }
    }

    // ---- Epilogue ----
    const float inv_lo = 1.f / l_lo;
    const float inv_hi = 1.f / l_hi;
#pragma unroll
    for (int j = 0; j < 32; j++) {
        const int col = s * 256 + (j >> 1) * 16 + (j & 1) * 8 + 2 * t;
        *(float2*)(O + (size_t)(qb * BM + p * 16 + g) * FD + col) =
            make_float2(oacc[j][0] * inv_lo, oacc[j][1] * inv_lo);
        *(float2*)(O + (size_t)(qb * BM + p * 16 + 8 + g) * FD + col) =
            make_float2(oacc[j][2] * inv_hi, oacc[j][3] * inv_hi);
    }
}

// ---------------------------------------------------------------------------
// kernel_launch
// ---------------------------------------------------------------------------
extern "C" void kernel_launch(void* const* d_in, const int* in_sizes, int n_in,
                              void* d_out, int out_size)
{
    const float* x  = (const float*)d_in[0];
    const float* Wq = (const float*)d_in[1];
    const float* bq = (const float*)d_in[2];
    const float* Wk = (const float*)d_in[3];
    const float* bk = (const float*)d_in[4];
    const float* Wv = (const float*)d_in[5];
    const float* bv = (const float*)d_in[6];
    const float* Wo = (const float*)d_in[7];
    const float* bo = (const float*)d_in[8];
    float* out = (float*)d_out;

    __nv_bfloat16 *pQ, *pK, *pV;
    float* pA;
    cudaGetSymbolAddress((void**)&pQ, g_Qb);
    cudaGetSymbolAddress((void**)&pK, g_Kb);
    cudaGetSymbolAddress((void**)&pV, g_Vb);
    cudaGetSymbolAddress((void**)&pA, g_att);

    cudaFuncSetAttribute(flash_kernel,
                         cudaFuncAttributeMaxDynamicSharedMemorySize, SMEM_TOTAL);

    dim3 blk(256);
    gemm_tf32_kernel<1><<<dim3(1, 128), blk>>>(x, Wq, bq, pQ, FD, MD);
    gemm_tf32_kernel<1><<<dim3(1, 128), blk>>>(x, Wk, bk, pK, FD, MD);
    gemm_tf32_kernel<1><<<dim3(4, 128), blk>>>(x, Wv, bv, pV, FD, FD);
    flash_kernel<<<NPTS / BM, 256, SMEM_TOTAL>>>(pQ, pK, pV, pA);
    gemm_tf32_kernel<0><<<dim3(4, 128), blk>>>(pA, Wo, bo, out, FD, FD);
}